// round 6
// baseline (speedup 1.0000x reference)
#include <cuda_runtime.h>
#include <cuda_bf16.h>

#define BB 64
#define TT 1024
#define DD 64
#define HH 4
#define SPLIT 8
#define RPC 128        // key rows per CTA (SPLIT*RPC = TT)
#define STRIDE 68
#define NEGF (-4294967296.0f)

// ---------------- kernel A smem layout (floats) ----------------
#define OFF_KS   0                // 128*68 = 8704
#define OFF_P4   8704             // 128 float4 = 512
#define OFF_ACC  9216             // 256 float4 = 1024
#define OFF_U    10240            // 256
#define OFF_Q0   10496            // 64
#define OFF_QH   10560            // 64
#define OFF_WRED 10624            // 32
#define OFF_MH   10656            // 4
#define ASM_FLOATS 10660
#define ASM_BYTES (ASM_FLOATS * 4)

// ---------------- kernel B smem layout (floats) ----------------
#define BF_WV    0                // 4096
#define BF_FW1   4096             // 2048  (fw1 col slice [64][32])
#define BF_FW2   6144             // 2048  (fw2 row slice [32][64])
#define BF_PACC  8192             // 2048  (512 float4)
#define BF_PART  10240            // 256
#define BF_SSM   10496            // 256
#define BF_QS    10752            // 64
#define BF_FB1   10816            // 32
#define BF_FB2   10848            // 64
#define BF_RES   10912            // 64
#define BF_HID   10976            // 32
#define BF_MS    11008            // 32
#define BF_LS    11040            // 32
#define BF_FS    11072            // 32
#define BF_SC    11104            // 4
#define BF_QMV   11108            // 4 (16B chunk holding query_mask int)
#define BSM_FLOATS 11112
#define BSM_BYTES (BSM_FLOATS * 4)

#define CP_ASYNC16(dst_u32, src) \
    asm volatile("cp.async.cg.shared.global [%0], [%1], 16;" :: "r"(dst_u32), "l"(src) : "memory")
#define CP_COMMIT() asm volatile("cp.async.commit_group;" ::: "memory")
#define CP_WAIT_ALL() asm volatile("cp.async.wait_group 0;" ::: "memory")

// cross-kernel scratch
__device__ float4 g_pacc[BB * SPLIT * DD];   // [b][split][d] -> 4 heads packed
__device__ float  g_pm[BB * SPLIT * HH];
__device__ float  g_pl[BB * SPLIT * HH];

__global__ __launch_bounds__(256) void attn_partial_kernel(
    const float* __restrict__ queries, const float* __restrict__ keys,
    const int* __restrict__ key_mask,
    const float* __restrict__ W_Q, const float* __restrict__ W_K,
    float* __restrict__ out)
{
    extern __shared__ float sm[];
    const unsigned sbase = (unsigned)__cvta_generic_to_shared(sm);

    float*  ks   = sm + OFF_KS;
    float4* p4   = (float4*)(sm + OFF_P4);
    float4* accm = (float4*)(sm + OFF_ACC);
    float*  u    = sm + OFF_U;
    float*  q0   = sm + OFF_Q0;
    float*  Qh   = sm + OFF_QH;
    float*  wred = sm + OFF_WRED;
    float*  mh   = sm + OFF_MH;

    const int split = blockIdx.x;
    const int b     = blockIdx.y;
    const int t     = threadIdx.x;
    const int k0    = split * RPC;
    const int lane  = t & 31;
    const int wid   = t >> 5;

    // ---- key tile DMA: 128 rows x 16 f4 = 2048 f4, 8 per thread ----
    {
        const float4* kg = (const float4*)(keys + ((size_t)b * TT + k0) * DD);
        #pragma unroll
        for (int i = 0; i < 8; i++) {
            int idx = t + i * 256;
            int row = idx >> 4, c = idx & 15;
            CP_ASYNC16(sbase + (row * STRIDE + c * 4) * 4, kg + idx);
        }
        CP_COMMIT();
    }
    int kmv = 1;
    if (t < RPC) kmv = key_mask[b * TT + k0 + t];
    if (t < 64) q0[t] = queries[(size_t)b * TT * DD + t];
    if (split == 0 && t >= 64 && t < 128) out[b * 64 + (t - 64)] = 0.f;
    __syncthreads();

    // ---- Qh = q0 @ W_Q (overlaps key DMA) ----
    {
        int j = t & 63, q = t >> 6;
        float a = 0.f;
        #pragma unroll
        for (int i = q * 16; i < q * 16 + 16; i++) a += q0[i] * W_Q[i * 64 + j];
        ((float*)accm)[t] = a;
    }
    __syncthreads();
    if (t < 64) {
        float* pr = (float*)accm;
        Qh[t] = pr[t] + pr[64 + t] + pr[128 + t] + pr[192 + t];
    }
    __syncthreads();

    // ---- u[d*4+h] = 0.25 * W_K[d][h-blk] . Qh[h-blk] ----
    {
        int d = t & 63, h = t >> 6;
        const float4* wr  = (const float4*)(W_K + d * 64 + h * 16);
        const float4* qh4 = (const float4*)(Qh + h * 16);
        float a = 0.f;
        #pragma unroll
        for (int c = 0; c < 4; c++) {
            float4 w = wr[c]; float4 q = qh4[c];
            a += w.x * q.x + w.y * q.y + w.z * q.z + w.w * q.w;
        }
        u[d * 4 + h] = a * 0.25f;
    }
    CP_WAIT_ALL();
    __syncthreads();

    // ---- scores for key row t (threads 0..127), 4 heads ----
    if (t < RPC) {
        float s0, s1, s2, s3;
        {
            const float4* krow = (const float4*)&ks[t * STRIDE];
            const float4* u4 = (const float4*)u;
            float a0 = 0.f, a1 = 0.f, a2 = 0.f, a3 = 0.f;
            #pragma unroll
            for (int c = 0; c < 16; c++) {
                float4 kv = krow[c];
                float4 ux = u4[4 * c + 0], uy = u4[4 * c + 1];
                float4 uz = u4[4 * c + 2], uw = u4[4 * c + 3];
                a0 += kv.x * ux.x + kv.y * uy.x + kv.z * uz.x + kv.w * uw.x;
                a1 += kv.x * ux.y + kv.y * uy.y + kv.z * uz.y + kv.w * uw.y;
                a2 += kv.x * ux.z + kv.y * uy.z + kv.z * uz.z + kv.w * uw.z;
                a3 += kv.x * ux.w + kv.y * uy.w + kv.z * uz.w + kv.w * uw.w;
            }
            bool masked = (kmv != 1) || ((k0 + t) == 0);
            s0 = masked ? NEGF : a0;
            s1 = masked ? NEGF : a1;
            s2 = masked ? NEGF : a2;
            s3 = masked ? NEGF : a3;
        }
        // warp max (warps 0-3)
        float m0 = s0, m1 = s1, m2 = s2, m3 = s3;
        #pragma unroll
        for (int o = 16; o; o >>= 1) {
            m0 = fmaxf(m0, __shfl_xor_sync(0xffffffffu, m0, o));
            m1 = fmaxf(m1, __shfl_xor_sync(0xffffffffu, m1, o));
            m2 = fmaxf(m2, __shfl_xor_sync(0xffffffffu, m2, o));
            m3 = fmaxf(m3, __shfl_xor_sync(0xffffffffu, m3, o));
        }
        if (lane == 0) {
            wred[wid * 4 + 0] = m0; wred[wid * 4 + 1] = m1;
            wred[wid * 4 + 2] = m2; wred[wid * 4 + 3] = m3;
        }
        __syncwarp();
        // stash scores in p4 temporarily so we can re-read after block max
        p4[t] = make_float4(s0, s1, s2, s3);
    }
    __syncthreads();
    if (t < 4) {
        float m = wred[t];
        #pragma unroll
        for (int w = 1; w < 4; w++) m = fmaxf(m, wred[w * 4 + t]);
        mh[t] = m;
    }
    __syncthreads();

    if (t < RPC) {
        float4 s = p4[t];
        float p0 = __expf(s.x - mh[0]);
        float p1 = __expf(s.y - mh[1]);
        float p2 = __expf(s.z - mh[2]);
        float p3 = __expf(s.w - mh[3]);
        p4[t] = make_float4(p0, p1, p2, p3);
        float l0 = p0, l1 = p1, l2 = p2, l3 = p3;
        #pragma unroll
        for (int o = 16; o; o >>= 1) {
            l0 += __shfl_xor_sync(0xffffffffu, l0, o);
            l1 += __shfl_xor_sync(0xffffffffu, l1, o);
            l2 += __shfl_xor_sync(0xffffffffu, l2, o);
            l3 += __shfl_xor_sync(0xffffffffu, l3, o);
        }
        if (lane == 0) {
            wred[wid * 4 + 0] = l0; wred[wid * 4 + 1] = l1;
            wred[wid * 4 + 2] = l2; wred[wid * 4 + 3] = l3;
        }
    }
    __syncthreads();
    if (t < 4) {
        float l = wred[t];
        #pragma unroll
        for (int w = 1; w < 4; w++) l += wred[w * 4 + t];
        g_pm[(b * SPLIT + split) * HH + t] = mh[t];
        g_pl[(b * SPLIT + split) * HH + t] = l;
    }

    // ---- weighted key sum: thread (d = t&63, quarter q = t>>6) -> 32 rows ----
    {
        int d = t & 63, q = t >> 6;
        float ax = 0.f, ay = 0.f, az = 0.f, aw = 0.f;
        const int kb = q * 32;
        #pragma unroll 4
        for (int kk = 0; kk < 32; kk++) {
            float kv = ks[(kb + kk) * STRIDE + d];
            float4 p = p4[kb + kk];
            ax += p.x * kv; ay += p.y * kv; az += p.z * kv; aw += p.w * kv;
        }
        accm[t] = make_float4(ax, ay, az, aw);
    }
    __syncthreads();
    if (t < 64) {
        float4 a = accm[t], c = accm[64 + t], d4 = accm[128 + t], e = accm[192 + t];
        float4 r;
        r.x = a.x + c.x + d4.x + e.x;
        r.y = a.y + c.y + d4.y + e.y;
        r.z = a.z + c.z + d4.z + e.z;
        r.w = a.w + c.w + d4.w + e.w;
        g_pacc[(b * SPLIT + split) * DD + t] = r;
    }
}

// Kernel B: 8 CTAs per batch; CTA q owns hidden slice [32q, 32q+32).
// All loads via cp.async (one deep wave, no register MLP cap).
__global__ __launch_bounds__(256) void combine_ffn_kernel(
    const float* __restrict__ queries, const int* __restrict__ query_mask,
    const float* __restrict__ W_V,
    const float* __restrict__ fw1, const float* __restrict__ fw2,
    const float* __restrict__ fb1, const float* __restrict__ fb2,
    float* __restrict__ out)
{
    extern __shared__ float sm[];
    const unsigned sbase = (unsigned)__cvta_generic_to_shared(sm);
    const int q = blockIdx.x;   // hidden-slice 0..7
    const int b = blockIdx.y;
    const int t = threadIdx.x;

    float*  wv_s   = sm + BF_WV;
    float*  fw1_s  = sm + BF_FW1;
    float*  fw2_s  = sm + BF_FW2;
    float4* pacc_s = (float4*)(sm + BF_PACC);
    float*  part_s = sm + BF_PART;
    float*  s_sm   = sm + BF_SSM;
    float*  q_s    = sm + BF_QS;
    float*  fb1_s  = sm + BF_FB1;
    float*  fb2_s  = sm + BF_FB2;
    float*  res_s  = sm + BF_RES;
    float*  hid_s  = sm + BF_HID;
    float*  m_s    = sm + BF_MS;
    float*  l_s    = sm + BF_LS;
    float*  f_s    = sm + BF_FS;
    float*  sc_s   = sm + BF_SC;

    // ---- prefetch (single cp.async wave) ----
    {
        const float4* gv = (const float4*)W_V;                       // 1024 f4
        const float4* g1 = (const float4*)fw1;                       // row = 64 f4
        const float4* g2 = (const float4*)(fw2 + q * 32 * 64);       // 512 f4
        const float4* gp = g_pacc + b * (SPLIT * DD);                // 512 f4

        #pragma unroll
        for (int i = 0; i < 4; i++) {
            int idx = t + i * 256;
            CP_ASYNC16(sbase + (BF_WV + idx * 4) * 4, gv + idx);
        }
        // fw1 col slice [64 rows][32 cols]: f4 idx = row*8 + c ; src row*64 + q*8 + c
        #pragma unroll
        for (int i = 0; i < 2; i++) {
            int idx = t + i * 256;
            int row = idx >> 3, c = idx & 7;
            CP_ASYNC16(sbase + (BF_FW1 + idx * 4) * 4, g1 + row * 64 + q * 8 + c);
        }
        #pragma unroll
        for (int i = 0; i < 2; i++) {
            int idx = t + i * 256;
            CP_ASYNC16(sbase + (BF_FW2 + idx * 4) * 4, g2 + idx);
        }
        #pragma unroll
        for (int i = 0; i < 2; i++) {
            int idx = t + i * 256;
            CP_ASYNC16(sbase + (BF_PACC + idx * 4) * 4, gp + idx);
        }
        if (t < 8) {
            CP_ASYNC16(sbase + (BF_MS + t * 4) * 4, ((const float4*)(g_pm + b * 32)) + t);
        } else if (t < 16) {
            CP_ASYNC16(sbase + (BF_LS + (t - 8) * 4) * 4, ((const float4*)(g_pl + b * 32)) + (t - 8));
        } else if (t < 32) {
            CP_ASYNC16(sbase + (BF_QS + (t - 16) * 4) * 4,
                       ((const float4*)(queries + (size_t)b * TT * DD)) + (t - 16));
        } else if (t < 40) {
            CP_ASYNC16(sbase + (BF_FB1 + (t - 32) * 4) * 4, ((const float4*)(fb1 + q * 32)) + (t - 32));
        } else if (t < 56) {
            CP_ASYNC16(sbase + (BF_FB2 + (t - 40) * 4) * 4, ((const float4*)fb2) + (t - 40));
        } else if (t == 56) {
            CP_ASYNC16(sbase + BF_QMV * 4, (const float4*)(query_mask + b * TT));
        }
        CP_COMMIT();
    }
    CP_WAIT_ALL();
    __syncthreads();

    // ---- softmax split combine (8 splits) ----
    if (t < HH) {
        float M = m_s[t];
        #pragma unroll
        for (int s = 1; s < SPLIT; s++) M = fmaxf(M, m_s[s * HH + t]);
        float L = 0.f;
        #pragma unroll
        for (int s = 0; s < SPLIT; s++) {
            float f = __expf(m_s[s * HH + t] - M);
            f_s[s * HH + t] = f;
            L += l_s[s * HH + t] * f;
        }
        float qm = (float)((const int*)(sm + BF_QMV))[0];
        sc_s[t] = qm / L;
    }
    __syncthreads();

    {
        int d = t & 63, h = t >> 6;
        const float* pa = (const float*)pacc_s;
        float S = 0.f;
        #pragma unroll
        for (int s = 0; s < SPLIT; s++)
            S += pa[(s * DD + d) * 4 + h] * f_s[s * HH + h];
        s_sm[h * DD + d] = S * sc_s[h];
    }
    __syncthreads();

    // res[j] = s[h(j)] @ W_V[:,j] + queries[b,0,j]
    {
        int j = t & 63, qq = t >> 6;
        int h = j >> 4;
        float a = 0.f;
        #pragma unroll
        for (int d = qq * 16; d < qq * 16 + 16; d++) a += s_sm[h * DD + d] * wv_s[d * 64 + j];
        part_s[t] = a;
    }
    __syncthreads();
    if (t < 64) {
        float o = part_s[t] + part_s[64 + t] + part_s[128 + t] + part_s[192 + t];
        res_s[t] = o + q_s[t];
    }
    __syncthreads();

    // hidden slice (32 units): thread (m = t&31, jq = t>>5) -> 8 j each
    {
        int m = t & 31, jq = t >> 5;
        float a = 0.f;
        #pragma unroll
        for (int j = jq * 8; j < jq * 8 + 8; j++) a += res_s[j] * fw1_s[j * 32 + m];
        part_s[jq * 32 + m] = a;
    }
    __syncthreads();
    if (t < 32) {
        float a = fb1_s[t];
        #pragma unroll
        for (int w = 0; w < 8; w++) a += part_s[w * 32 + t];
        hid_s[t] = (a > 0.f) ? a : 0.2f * a;
    }
    __syncthreads();

    // output partial: thread (j = t&63, mq = t>>6) -> 8 m each
    {
        int j = t & 63, mq = t >> 6;
        float a = 0.f;
        #pragma unroll
        for (int m2 = mq * 8; m2 < mq * 8 + 8; m2++) a += hid_s[m2] * fw2_s[m2 * 64 + j];
        part_s[t] = a;
    }
    __syncthreads();
    if (t < 64) {
        float v = part_s[t] + part_s[64 + t] + part_s[128 + t] + part_s[192 + t];
        if (q == 0) v += res_s[t] + fb2_s[t];
        atomicAdd(&out[b * 64 + t], v);
    }
}

extern "C" void kernel_launch(void* const* d_in, const int* in_sizes, int n_in,
                              void* d_out, int out_size)
{
    const float* queries = (const float*)d_in[0];
    const float* keys    = (const float*)d_in[1];
    const int*   qmask   = (const int*)d_in[2];
    const int*   kmask   = (const int*)d_in[3];
    const float* W_Q     = (const float*)d_in[4];
    const float* W_K     = (const float*)d_in[5];
    const float* W_V     = (const float*)d_in[6];
    const float* fw1     = (const float*)d_in[7];
    const float* fw2     = (const float*)d_in[8];
    const float* fb1     = (const float*)d_in[9];
    const float* fb2     = (const float*)d_in[10];
    float* out = (float*)d_out;

    cudaFuncSetAttribute(attn_partial_kernel,
                         cudaFuncAttributeMaxDynamicSharedMemorySize, ASM_BYTES);
    cudaFuncSetAttribute(combine_ffn_kernel,
                         cudaFuncAttributeMaxDynamicSharedMemorySize, BSM_BYTES);

    attn_partial_kernel<<<dim3(SPLIT, BB), 256, ASM_BYTES>>>(queries, keys, kmask, W_Q, W_K, out);
    combine_ffn_kernel<<<dim3(SPLIT, BB), 256, BSM_BYTES>>>(queries, qmask, W_V, fw1, fw2, fb1, fb2, out);
}

// round 7
// speedup vs baseline: 1.0745x; 1.0745x over previous
#include <cuda_runtime.h>
#include <cuda_bf16.h>

#define BB 64
#define TT 1024
#define DD 64
#define HH 4
#define SPLIT 8
#define RPC 128
#define STRIDE 68
#define NEGF (-4294967296.0f)

// ---------------- kernel A smem layout (floats) ----------------
#define OFF_KS   0                // 128*68 = 8704
#define OFF_P4   8704             // 512
#define OFF_ACC  9216             // 1024
#define OFF_U    10240            // 256
#define OFF_WRED 10496            // 32
#define OFF_MH   10528            // 4
#define ASM_FLOATS 10532
#define ASM_BYTES (ASM_FLOATS * 4)

// ---------------- kernel B smem layout (floats) ----------------
#define BF_WV    0                // 4096
#define BF_FW1   4096             // 16384
#define BF_FW2   20480            // 16384
#define BF_PACC  36864            // 2048  ([s][h][d] planar)
#define BF_FB1   38912            // 256
#define BF_FB2   39168            // 64
#define BF_Q0    39232            // 64
#define BF_MS    39296            // 32
#define BF_LS    39328            // 32
#define BF_FS    39360            // 32
#define BF_SC    39392            // 4
#define BF_QM    39396            // 4 (16B chunk holding query_mask int)
#define BF_SSM   39400            // 256
#define BF_PART  39656            // 256
#define BF_RES   39912            // 64
#define BF_HID   39976            // 256
#define BSM_FLOATS 40232
#define BSM_BYTES (BSM_FLOATS * 4)

#define CP_ASYNC16(dst_u32, src) \
    asm volatile("cp.async.cg.shared.global [%0], [%1], 16;" :: "r"(dst_u32), "l"(src) : "memory")
#define CP_COMMIT() asm volatile("cp.async.commit_group;" ::: "memory")
#define CP_WAIT_GROUP(n) asm volatile("cp.async.wait_group %0;" :: "n"(n) : "memory")

// cross-kernel scratch
__device__ float g_u[BB * 256];                      // [b][d*4+h]
__device__ float g_pacc[BB * SPLIT * HH * DD];       // [b][s][h][d] planar
__device__ float g_pm[BB * SPLIT * HH];              // [b][s][h]
__device__ float g_pl[BB * SPLIT * HH];

// ============ K0: u[b][d][h] = 0.25 * W_K[d][h-blk] . (q0 @ W_Q)[h-blk] =====
__global__ __launch_bounds__(64) void precompute_u_kernel(
    const float* __restrict__ queries,
    const float* __restrict__ W_Q, const float* __restrict__ W_K)
{
    __shared__ float q0[64];
    __shared__ float Qh[64];
    const int b = blockIdx.x;
    const int t = threadIdx.x;

    q0[t] = queries[(size_t)b * TT * DD + t];
    __syncthreads();

    float a = 0.f;
    #pragma unroll
    for (int i = 0; i < 64; i++) a += q0[i] * W_Q[i * 64 + t];
    Qh[t] = a;
    __syncthreads();

    // thread t = row d of W_K
    const float4* wr  = (const float4*)(W_K + t * 64);
    const float4* qh4 = (const float4*)Qh;
    float acc[HH];
    #pragma unroll
    for (int h = 0; h < HH; h++) {
        float s = 0.f;
        #pragma unroll
        for (int c = 0; c < 4; c++) {
            float4 w = wr[h * 4 + c];
            float4 q = qh4[h * 4 + c];
            s += w.x * q.x + w.y * q.y + w.z * q.z + w.w * q.w;
        }
        acc[h] = s * 0.25f;
    }
    ((float4*)g_u)[b * 64 + t] = make_float4(acc[0], acc[1], acc[2], acc[3]);
}

// ============ A: attention partials over a 128-key slice =====================
__global__ __launch_bounds__(256) void attn_partial_kernel(
    const float* __restrict__ keys, const int* __restrict__ key_mask)
{
    extern __shared__ float sm[];
    const unsigned sbase = (unsigned)__cvta_generic_to_shared(sm);

    float*  ks   = sm + OFF_KS;
    float4* p4   = (float4*)(sm + OFF_P4);
    float4* accm = (float4*)(sm + OFF_ACC);
    float*  u    = sm + OFF_U;
    float*  wred = sm + OFF_WRED;
    float*  mh   = sm + OFF_MH;

    const int split = blockIdx.x;
    const int b     = blockIdx.y;
    const int t     = threadIdx.x;
    const int k0    = split * RPC;
    const int lane  = t & 31;
    const int wid   = t >> 5;

    // key tile DMA: 128 rows x 16 f4 = 2048 f4, 8 per thread
    {
        const float4* kg = (const float4*)(keys + ((size_t)b * TT + k0) * DD);
        #pragma unroll
        for (int i = 0; i < 8; i++) {
            int idx = t + i * 256;
            int row = idx >> 4, c = idx & 15;
            CP_ASYNC16(sbase + (row * STRIDE + c * 4) * 4, kg + idx);
        }
        CP_COMMIT();
    }
    int kmv = 1;
    if (t < RPC) kmv = key_mask[b * TT + k0 + t];
    if (t < 64) ((float4*)u)[t] = ((const float4*)g_u)[b * 64 + t];   // precomputed
    CP_WAIT_GROUP(0);
    __syncthreads();

    // scores for key row t (threads 0..127), 4 heads
    if (t < RPC) {
        const float4* krow = (const float4*)&ks[t * STRIDE];
        const float4* u4 = (const float4*)u;
        float a0 = 0.f, a1 = 0.f, a2 = 0.f, a3 = 0.f;
        #pragma unroll
        for (int c = 0; c < 16; c++) {
            float4 kv = krow[c];
            float4 ux = u4[4 * c + 0], uy = u4[4 * c + 1];
            float4 uz = u4[4 * c + 2], uw = u4[4 * c + 3];
            a0 += kv.x * ux.x + kv.y * uy.x + kv.z * uz.x + kv.w * uw.x;
            a1 += kv.x * ux.y + kv.y * uy.y + kv.z * uz.y + kv.w * uw.y;
            a2 += kv.x * ux.z + kv.y * uy.z + kv.z * uz.z + kv.w * uw.z;
            a3 += kv.x * ux.w + kv.y * uy.w + kv.z * uz.w + kv.w * uw.w;
        }
        bool masked = (kmv != 1) || ((k0 + t) == 0);
        float s0 = masked ? NEGF : a0;
        float s1 = masked ? NEGF : a1;
        float s2 = masked ? NEGF : a2;
        float s3 = masked ? NEGF : a3;

        float m0 = s0, m1 = s1, m2 = s2, m3 = s3;
        #pragma unroll
        for (int o = 16; o; o >>= 1) {
            m0 = fmaxf(m0, __shfl_xor_sync(0xffffffffu, m0, o));
            m1 = fmaxf(m1, __shfl_xor_sync(0xffffffffu, m1, o));
            m2 = fmaxf(m2, __shfl_xor_sync(0xffffffffu, m2, o));
            m3 = fmaxf(m3, __shfl_xor_sync(0xffffffffu, m3, o));
        }
        if (lane == 0) {
            wred[wid * 4 + 0] = m0; wred[wid * 4 + 1] = m1;
            wred[wid * 4 + 2] = m2; wred[wid * 4 + 3] = m3;
        }
        p4[t] = make_float4(s0, s1, s2, s3);
    }
    __syncthreads();
    if (t < 4) {
        float m = wred[t];
        #pragma unroll
        for (int w = 1; w < 4; w++) m = fmaxf(m, wred[w * 4 + t]);
        mh[t] = m;
    }
    __syncthreads();

    if (t < RPC) {
        float4 s = p4[t];
        float p0 = __expf(s.x - mh[0]);
        float p1 = __expf(s.y - mh[1]);
        float p2 = __expf(s.z - mh[2]);
        float p3 = __expf(s.w - mh[3]);
        p4[t] = make_float4(p0, p1, p2, p3);
        float l0 = p0, l1 = p1, l2 = p2, l3 = p3;
        #pragma unroll
        for (int o = 16; o; o >>= 1) {
            l0 += __shfl_xor_sync(0xffffffffu, l0, o);
            l1 += __shfl_xor_sync(0xffffffffu, l1, o);
            l2 += __shfl_xor_sync(0xffffffffu, l2, o);
            l3 += __shfl_xor_sync(0xffffffffu, l3, o);
        }
        if (lane == 0) {
            wred[wid * 4 + 0] = l0; wred[wid * 4 + 1] = l1;
            wred[wid * 4 + 2] = l2; wred[wid * 4 + 3] = l3;
        }
    }
    __syncthreads();
    if (t < 4) {
        float l = wred[t];
        #pragma unroll
        for (int w = 1; w < 4; w++) l += wred[w * 4 + t];
        g_pm[(b * SPLIT + split) * HH + t] = mh[t];
        g_pl[(b * SPLIT + split) * HH + t] = l;
    }

    // weighted key sum: thread (d = t&63, quarter = t>>6) covers 32 rows
    {
        int d = t & 63, q = t >> 6;
        float ax = 0.f, ay = 0.f, az = 0.f, aw = 0.f;
        const int kb = q * 32;
        #pragma unroll 4
        for (int kk = 0; kk < 32; kk++) {
            float kv = ks[(kb + kk) * STRIDE + d];
            float4 p = p4[kb + kk];
            ax += p.x * kv; ay += p.y * kv; az += p.z * kv; aw += p.w * kv;
        }
        accm[t] = make_float4(ax, ay, az, aw);
    }
    __syncthreads();
    if (t < 64) {
        float4 a = accm[t], c = accm[64 + t], d4 = accm[128 + t], e = accm[192 + t];
        float* gp = g_pacc + (b * SPLIT + split) * (HH * DD);
        gp[0 * DD + t] = a.x + c.x + d4.x + e.x;   // planar [h][d]
        gp[1 * DD + t] = a.y + c.y + d4.y + e.y;
        gp[2 * DD + t] = a.z + c.z + d4.z + e.z;
        gp[3 * DD + t] = a.w + c.w + d4.w + e.w;
    }
}

// ============ B: combine + FFN, one CTA per batch, staged cp.async ==========
__global__ __launch_bounds__(256) void combine_ffn_kernel(
    const float* __restrict__ queries, const int* __restrict__ query_mask,
    const float* __restrict__ W_V,
    const float* __restrict__ fw1, const float* __restrict__ fw2,
    const float* __restrict__ fb1, const float* __restrict__ fb2,
    float* __restrict__ out)
{
    extern __shared__ float sm[];
    const unsigned sbase = (unsigned)__cvta_generic_to_shared(sm);
    const int b = blockIdx.x;
    const int t = threadIdx.x;

    float* wv_s   = sm + BF_WV;
    float* fw1_s  = sm + BF_FW1;
    float* fw2_s  = sm + BF_FW2;
    float* pacc_s = sm + BF_PACC;
    float* fb1_s  = sm + BF_FB1;
    float* fb2_s  = sm + BF_FB2;
    float* q_s    = sm + BF_Q0;
    float* m_s    = sm + BF_MS;
    float* l_s    = sm + BF_LS;
    float* f_s    = sm + BF_FS;
    float* sc_s   = sm + BF_SC;
    float* s_sm   = sm + BF_SSM;
    float* part_s = sm + BF_PART;
    float* res_s  = sm + BF_RES;
    float* hid_s  = sm + BF_HID;

    // ---- G1: pacc + W_V + scalars (needed first) ----
    {
        const float4* gp = (const float4*)(g_pacc + b * (SPLIT * HH * DD));  // 512 f4
        const float4* gv = (const float4*)W_V;                               // 1024 f4
        #pragma unroll
        for (int i = 0; i < 2; i++) {
            int idx = t + i * 256;
            CP_ASYNC16(sbase + (BF_PACC + idx * 4) * 4, gp + idx);
        }
        #pragma unroll
        for (int i = 0; i < 4; i++) {
            int idx = t + i * 256;
            CP_ASYNC16(sbase + (BF_WV + idx * 4) * 4, gv + idx);
        }
        if (t < 8) {
            CP_ASYNC16(sbase + (BF_MS + t * 4) * 4, ((const float4*)(g_pm + b * 32)) + t);
        } else if (t < 16) {
            CP_ASYNC16(sbase + (BF_LS + (t - 8) * 4) * 4, ((const float4*)(g_pl + b * 32)) + (t - 8));
        } else if (t < 32) {
            CP_ASYNC16(sbase + (BF_Q0 + (t - 16) * 4) * 4,
                       ((const float4*)(queries + (size_t)b * TT * DD)) + (t - 16));
        } else if (t < 48) {
            CP_ASYNC16(sbase + (BF_FB2 + (t - 32) * 4) * 4, ((const float4*)fb2) + (t - 32));
        } else if (t == 48) {
            CP_ASYNC16(sbase + BF_QM * 4, (const float4*)(query_mask + b * TT));
        }
        CP_COMMIT();
    }
    // ---- G2: fw1 + fb1 ----
    {
        const float4* g1 = (const float4*)fw1;   // 4096 f4
        #pragma unroll
        for (int i = 0; i < 16; i++) {
            int idx = t + i * 256;
            CP_ASYNC16(sbase + (BF_FW1 + idx * 4) * 4, g1 + idx);
        }
        if (t < 64) CP_ASYNC16(sbase + (BF_FB1 + t * 4) * 4, ((const float4*)fb1) + t);
        CP_COMMIT();
    }
    // ---- G3: fw2 ----
    {
        const float4* g2 = (const float4*)fw2;   // 4096 f4
        #pragma unroll
        for (int i = 0; i < 16; i++) {
            int idx = t + i * 256;
            CP_ASYNC16(sbase + (BF_FW2 + idx * 4) * 4, g2 + idx);
        }
        CP_COMMIT();
    }

    CP_WAIT_GROUP(2);   // G1 ready
    __syncthreads();

    // ---- softmax split combine (warp 0; lane = s*4+h) ----
    if (t < 32) {
        float m = m_s[t], lv = l_s[t];
        float M = m;
        M = fmaxf(M, __shfl_xor_sync(0xffffffffu, M, 4));
        M = fmaxf(M, __shfl_xor_sync(0xffffffffu, M, 8));
        M = fmaxf(M, __shfl_xor_sync(0xffffffffu, M, 16));
        float f = __expf(m - M);
        f_s[t] = f;
        float L = lv * f;
        L += __shfl_xor_sync(0xffffffffu, L, 4);
        L += __shfl_xor_sync(0xffffffffu, L, 8);
        L += __shfl_xor_sync(0xffffffffu, L, 16);
        if (t < 4) {
            float qm = (float)((const int*)(sm + BF_QM))[0];
            sc_s[t] = qm / L;
        }
    }
    __syncthreads();

    // s[h][d] = (sum_s pacc[s][h][d] * f[s][h]) * qm/L
    {
        int d = t & 63, h = t >> 6;
        float S = 0.f;
        #pragma unroll
        for (int s = 0; s < SPLIT; s++)
            S += pacc_s[s * (HH * DD) + h * DD + d] * f_s[s * HH + h];
        s_sm[h * DD + d] = S * sc_s[h];
    }
    __syncthreads();

    // res[j] = s[h(j)] @ W_V[:,j] + queries[b,0,j]
    {
        int j = t & 63, q = t >> 6;
        int h = j >> 4;
        float a = 0.f;
        #pragma unroll
        for (int d = q * 16; d < q * 16 + 16; d++) a += s_sm[h * DD + d] * wv_s[d * 64 + j];
        part_s[t] = a;
    }
    __syncthreads();
    if (t < 64) {
        float o = part_s[t] + part_s[64 + t] + part_s[128 + t] + part_s[192 + t];
        res_s[t] = o + q_s[t];
    }
    CP_WAIT_GROUP(1);   // fw1 ready
    __syncthreads();

    // hidden[m] = leaky_relu(res @ fw1[:,m] + fb1[m]) ; thread = m
    {
        float a = fb1_s[t];
        #pragma unroll
        for (int j = 0; j < 64; j++) a += res_s[j] * fw1_s[j * 256 + t];
        hid_s[t] = (a > 0.f) ? a : 0.2f * a;
    }
    CP_WAIT_GROUP(0);   // fw2 ready
    __syncthreads();

    // out[j] = res[j] + fb2[j] + hid @ fw2[:,j]
    {
        int j = t & 63, mq = t >> 6;
        float a = 0.f;
        #pragma unroll
        for (int m = mq * 64; m < mq * 64 + 64; m++) a += hid_s[m] * fw2_s[m * 64 + j];
        part_s[t] = a;
    }
    __syncthreads();
    if (t < 64) {
        out[b * 64 + t] = res_s[t] + fb2_s[t]
                        + part_s[t] + part_s[64 + t] + part_s[128 + t] + part_s[192 + t];
    }
}

extern "C" void kernel_launch(void* const* d_in, const int* in_sizes, int n_in,
                              void* d_out, int out_size)
{
    const float* queries = (const float*)d_in[0];
    const float* keys    = (const float*)d_in[1];
    const int*   qmask   = (const int*)d_in[2];
    const int*   kmask   = (const int*)d_in[3];
    const float* W_Q     = (const float*)d_in[4];
    const float* W_K     = (const float*)d_in[5];
    const float* W_V     = (const float*)d_in[6];
    const float* fw1     = (const float*)d_in[7];
    const float* fw2     = (const float*)d_in[8];
    const float* fb1     = (const float*)d_in[9];
    const float* fb2     = (const float*)d_in[10];
    float* out = (float*)d_out;

    cudaFuncSetAttribute(attn_partial_kernel,
                         cudaFuncAttributeMaxDynamicSharedMemorySize, ASM_BYTES);
    cudaFuncSetAttribute(combine_ffn_kernel,
                         cudaFuncAttributeMaxDynamicSharedMemorySize, BSM_BYTES);

    precompute_u_kernel<<<BB, 64>>>(queries, W_Q, W_K);
    attn_partial_kernel<<<dim3(SPLIT, BB), 256, ASM_BYTES>>>(keys, kmask);
    combine_ffn_kernel<<<BB, 256, BSM_BYTES>>>(queries, qmask, W_V, fw1, fw2, fb1, fb2, out);
}

// round 8
// speedup vs baseline: 1.1248x; 1.0468x over previous
#include <cuda_runtime.h>
#include <cuda_bf16.h>

#define BB 64
#define TT 1024
#define DD 64
#define HH 4
#define SPLIT 8
#define RPC 128
#define STRIDE 68
#define NEGF (-4294967296.0f)

// ---------------- kernel A smem layout (floats) ----------------
#define OFF_KS   0                // 128*68 = 8704
#define OFF_P4   8704             // 512
#define OFF_ACC  9216             // 1024
#define OFF_U    10240            // 256
#define OFF_WRED 10496            // 32
#define OFF_MH   10528            // 4
#define ASM_FLOATS 10532
#define ASM_BYTES (ASM_FLOATS * 4)

// ---------------- kernel B smem layout (floats) ----------------
#define BF_WV    0                // 4096
#define BF_FW1   4096             // 16384
#define BF_FW2   20480            // 16384
#define BF_PACC  36864            // 2048  ([s][h][d] planar)
#define BF_FB1   38912            // 256
#define BF_FB2   39168            // 64
#define BF_Q0    39232            // 64
#define BF_MS    39296            // 32
#define BF_LS    39328            // 32
#define BF_FS    39360            // 32
#define BF_SC    39392            // 4
#define BF_QM    39396            // 4
#define BF_SSM   39400            // 256
#define BF_PART  39656            // 256
#define BF_RES   39912            // 64
#define BF_HID   39976            // 256
#define BSM_FLOATS 40232
#define BSM_BYTES (BSM_FLOATS * 4)

#define CP_ASYNC16(dst_u32, src) \
    asm volatile("cp.async.cg.shared.global [%0], [%1], 16;" :: "r"(dst_u32), "l"(src) : "memory")
#define CP_COMMIT() asm volatile("cp.async.commit_group;" ::: "memory")
#define CP_WAIT_GROUP(n) asm volatile("cp.async.wait_group %0;" :: "n"(n) : "memory")

// cross-kernel scratch
__device__ float g_u[BB * 256];                      // [b][d*4+h]
__device__ float g_pacc[BB * SPLIT * HH * DD];       // [b][s][h][d] planar
__device__ float g_pm[BB * SPLIT * HH];
__device__ float g_pl[BB * SPLIT * HH];

// ============ K0: u[b] = 0.25 * W_K-fold of (q0 @ W_Q), 256 threads =========
// smem: W_K staged via cp.async with stride-68 rows (conflict-free LDS.128).
__global__ __launch_bounds__(256) void precompute_u_kernel(
    const float* __restrict__ queries,
    const float* __restrict__ W_Q, const float* __restrict__ W_K)
{
    __shared__ float wk_s[64 * STRIDE];   // row d at d*STRIDE
    __shared__ float q0[64];
    __shared__ float part[256];
    __shared__ float Qh[64];

    const int b = blockIdx.x;
    const int t = threadIdx.x;
    const unsigned sbase = (unsigned)__cvta_generic_to_shared(wk_s);

    // W_K DMA: 1024 f4, 4 per thread, padded rows (hides behind Qh phase)
    {
        const float4* gk = (const float4*)W_K;
        #pragma unroll
        for (int i = 0; i < 4; i++) {
            int idx = t + i * 256;          // f4 index: row = idx>>4, col = idx&15
            int row = idx >> 4, c = idx & 15;
            CP_ASYNC16(sbase + (row * STRIDE + c * 4) * 4, gk + idx);
        }
        CP_COMMIT();
    }
    if (t < 16) ((float4*)q0)[t] = ((const float4*)(queries + (size_t)b * TT * DD))[t];
    __syncthreads();

    // Qh partial: thread (j = t&63, quarter = t>>6), 16 W_Q loads each (MLP 16)
    {
        int j = t & 63, q = t >> 6;
        float a = 0.f;
        #pragma unroll
        for (int i = q * 16; i < q * 16 + 16; i++) a += q0[i] * W_Q[i * 64 + j];
        part[t] = a;
    }
    __syncthreads();
    if (t < 64) Qh[t] = part[t] + part[64 + t] + part[128 + t] + part[192 + t];
    CP_WAIT_GROUP(0);
    __syncthreads();

    // u[d*4+h]: thread (d = t&63, h = t>>6); W_K from smem, Qh broadcast
    {
        int d = t & 63, h = t >> 6;
        const float4* wr  = (const float4*)(wk_s + d * STRIDE + h * 16);
        const float4* qh4 = (const float4*)(Qh + h * 16);
        float s = 0.f;
        #pragma unroll
        for (int c = 0; c < 4; c++) {
            float4 w = wr[c]; float4 q = qh4[c];
            s += w.x * q.x + w.y * q.y + w.z * q.z + w.w * q.w;
        }
        g_u[b * 256 + d * 4 + h] = s * 0.25f;
    }
}

// ============ A: attention partials over a 128-key slice =====================
__global__ __launch_bounds__(256) void attn_partial_kernel(
    const float* __restrict__ keys, const int* __restrict__ key_mask)
{
    extern __shared__ float sm[];
    const unsigned sbase = (unsigned)__cvta_generic_to_shared(sm);

    float*  ks   = sm + OFF_KS;
    float4* p4   = (float4*)(sm + OFF_P4);
    float4* accm = (float4*)(sm + OFF_ACC);
    float*  u    = sm + OFF_U;
    float*  wred = sm + OFF_WRED;
    float*  mh   = sm + OFF_MH;

    const int split = blockIdx.x;
    const int b     = blockIdx.y;
    const int t     = threadIdx.x;
    const int k0    = split * RPC;
    const int lane  = t & 31;
    const int wid   = t >> 5;

    // key tile DMA: 128 rows x 16 f4 = 2048 f4, 8 per thread
    {
        const float4* kg = (const float4*)(keys + ((size_t)b * TT + k0) * DD);
        #pragma unroll
        for (int i = 0; i < 8; i++) {
            int idx = t + i * 256;
            int row = idx >> 4, c = idx & 15;
            CP_ASYNC16(sbase + (row * STRIDE + c * 4) * 4, kg + idx);
        }
        CP_COMMIT();
    }
    int kmv = 1;
    if (t < RPC) kmv = key_mask[b * TT + k0 + t];
    if (t < 64) ((float4*)u)[t] = ((const float4*)g_u)[b * 64 + t];
    CP_WAIT_GROUP(0);
    __syncthreads();

    // scores for key row t (threads 0..127), 4 heads
    if (t < RPC) {
        const float4* krow = (const float4*)&ks[t * STRIDE];
        const float4* u4 = (const float4*)u;
        float a0 = 0.f, a1 = 0.f, a2 = 0.f, a3 = 0.f;
        #pragma unroll
        for (int c = 0; c < 16; c++) {
            float4 kv = krow[c];
            float4 ux = u4[4 * c + 0], uy = u4[4 * c + 1];
            float4 uz = u4[4 * c + 2], uw = u4[4 * c + 3];
            a0 += kv.x * ux.x + kv.y * uy.x + kv.z * uz.x + kv.w * uw.x;
            a1 += kv.x * ux.y + kv.y * uy.y + kv.z * uz.y + kv.w * uw.y;
            a2 += kv.x * ux.z + kv.y * uy.z + kv.z * uz.z + kv.w * uw.z;
            a3 += kv.x * ux.w + kv.y * uy.w + kv.z * uz.w + kv.w * uw.w;
        }
        bool masked = (kmv != 1) || ((k0 + t) == 0);
        float s0 = masked ? NEGF : a0;
        float s1 = masked ? NEGF : a1;
        float s2 = masked ? NEGF : a2;
        float s3 = masked ? NEGF : a3;

        float m0 = s0, m1 = s1, m2 = s2, m3 = s3;
        #pragma unroll
        for (int o = 16; o; o >>= 1) {
            m0 = fmaxf(m0, __shfl_xor_sync(0xffffffffu, m0, o));
            m1 = fmaxf(m1, __shfl_xor_sync(0xffffffffu, m1, o));
            m2 = fmaxf(m2, __shfl_xor_sync(0xffffffffu, m2, o));
            m3 = fmaxf(m3, __shfl_xor_sync(0xffffffffu, m3, o));
        }
        if (lane == 0) {
            wred[wid * 4 + 0] = m0; wred[wid * 4 + 1] = m1;
            wred[wid * 4 + 2] = m2; wred[wid * 4 + 3] = m3;
        }
        p4[t] = make_float4(s0, s1, s2, s3);
    }
    __syncthreads();
    if (t < 4) {
        float m = wred[t];
        #pragma unroll
        for (int w = 1; w < 4; w++) m = fmaxf(m, wred[w * 4 + t]);
        mh[t] = m;
    }
    __syncthreads();

    if (t < RPC) {
        float4 s = p4[t];
        float p0 = __expf(s.x - mh[0]);
        float p1 = __expf(s.y - mh[1]);
        float p2 = __expf(s.z - mh[2]);
        float p3 = __expf(s.w - mh[3]);
        p4[t] = make_float4(p0, p1, p2, p3);
        float l0 = p0, l1 = p1, l2 = p2, l3 = p3;
        #pragma unroll
        for (int o = 16; o; o >>= 1) {
            l0 += __shfl_xor_sync(0xffffffffu, l0, o);
            l1 += __shfl_xor_sync(0xffffffffu, l1, o);
            l2 += __shfl_xor_sync(0xffffffffu, l2, o);
            l3 += __shfl_xor_sync(0xffffffffu, l3, o);
        }
        if (lane == 0) {
            wred[wid * 4 + 0] = l0; wred[wid * 4 + 1] = l1;
            wred[wid * 4 + 2] = l2; wred[wid * 4 + 3] = l3;
        }
    }
    __syncthreads();
    if (t < 4) {
        float l = wred[t];
        #pragma unroll
        for (int w = 1; w < 4; w++) l += wred[w * 4 + t];
        g_pm[(b * SPLIT + split) * HH + t] = mh[t];
        g_pl[(b * SPLIT + split) * HH + t] = l;
    }

    // weighted key sum
    {
        int d = t & 63, q = t >> 6;
        float ax = 0.f, ay = 0.f, az = 0.f, aw = 0.f;
        const int kb = q * 32;
        #pragma unroll 4
        for (int kk = 0; kk < 32; kk++) {
            float kv = ks[(kb + kk) * STRIDE + d];
            float4 p = p4[kb + kk];
            ax += p.x * kv; ay += p.y * kv; az += p.z * kv; aw += p.w * kv;
        }
        accm[t] = make_float4(ax, ay, az, aw);
    }
    __syncthreads();
    if (t < 64) {
        float4 a = accm[t], c = accm[64 + t], d4 = accm[128 + t], e = accm[192 + t];
        float* gp = g_pacc + (b * SPLIT + split) * (HH * DD);
        gp[0 * DD + t] = a.x + c.x + d4.x + e.x;
        gp[1 * DD + t] = a.y + c.y + d4.y + e.y;
        gp[2 * DD + t] = a.z + c.z + d4.z + e.z;
        gp[3 * DD + t] = a.w + c.w + d4.w + e.w;
    }
}

// ============ B: combine + FFN, one CTA per batch, staged cp.async ==========
__global__ __launch_bounds__(256) void combine_ffn_kernel(
    const float* __restrict__ queries, const int* __restrict__ query_mask,
    const float* __restrict__ W_V,
    const float* __restrict__ fw1, const float* __restrict__ fw2,
    const float* __restrict__ fb1, const float* __restrict__ fb2,
    float* __restrict__ out)
{
    extern __shared__ float sm[];
    const unsigned sbase = (unsigned)__cvta_generic_to_shared(sm);
    const int b = blockIdx.x;
    const int t = threadIdx.x;

    float* wv_s   = sm + BF_WV;
    float* fw1_s  = sm + BF_FW1;
    float* fw2_s  = sm + BF_FW2;
    float* pacc_s = sm + BF_PACC;
    float* fb1_s  = sm + BF_FB1;
    float* fb2_s  = sm + BF_FB2;
    float* q_s    = sm + BF_Q0;
    float* m_s    = sm + BF_MS;
    float* l_s    = sm + BF_LS;
    float* f_s    = sm + BF_FS;
    float* sc_s   = sm + BF_SC;
    float* s_sm   = sm + BF_SSM;
    float* part_s = sm + BF_PART;
    float* res_s  = sm + BF_RES;
    float* hid_s  = sm + BF_HID;

    // G1: pacc + W_V + scalars
    {
        const float4* gp = (const float4*)(g_pacc + b * (SPLIT * HH * DD));
        const float4* gv = (const float4*)W_V;
        #pragma unroll
        for (int i = 0; i < 2; i++) {
            int idx = t + i * 256;
            CP_ASYNC16(sbase + (BF_PACC + idx * 4) * 4, gp + idx);
        }
        #pragma unroll
        for (int i = 0; i < 4; i++) {
            int idx = t + i * 256;
            CP_ASYNC16(sbase + (BF_WV + idx * 4) * 4, gv + idx);
        }
        if (t < 8) {
            CP_ASYNC16(sbase + (BF_MS + t * 4) * 4, ((const float4*)(g_pm + b * 32)) + t);
        } else if (t < 16) {
            CP_ASYNC16(sbase + (BF_LS + (t - 8) * 4) * 4, ((const float4*)(g_pl + b * 32)) + (t - 8));
        } else if (t < 32) {
            CP_ASYNC16(sbase + (BF_Q0 + (t - 16) * 4) * 4,
                       ((const float4*)(queries + (size_t)b * TT * DD)) + (t - 16));
        } else if (t < 48) {
            CP_ASYNC16(sbase + (BF_FB2 + (t - 32) * 4) * 4, ((const float4*)fb2) + (t - 32));
        } else if (t == 48) {
            CP_ASYNC16(sbase + BF_QM * 4, (const float4*)(query_mask + b * TT));
        }
        CP_COMMIT();
    }
    // G2: fw1 + fb1
    {
        const float4* g1 = (const float4*)fw1;
        #pragma unroll
        for (int i = 0; i < 16; i++) {
            int idx = t + i * 256;
            CP_ASYNC16(sbase + (BF_FW1 + idx * 4) * 4, g1 + idx);
        }
        if (t < 64) CP_ASYNC16(sbase + (BF_FB1 + t * 4) * 4, ((const float4*)fb1) + t);
        CP_COMMIT();
    }
    // G3: fw2
    {
        const float4* g2 = (const float4*)fw2;
        #pragma unroll
        for (int i = 0; i < 16; i++) {
            int idx = t + i * 256;
            CP_ASYNC16(sbase + (BF_FW2 + idx * 4) * 4, g2 + idx);
        }
        CP_COMMIT();
    }

    CP_WAIT_GROUP(2);
    __syncthreads();

    // softmax split combine (warp 0; lane = s*4+h)
    if (t < 32) {
        float m = m_s[t], lv = l_s[t];
        float M = m;
        M = fmaxf(M, __shfl_xor_sync(0xffffffffu, M, 4));
        M = fmaxf(M, __shfl_xor_sync(0xffffffffu, M, 8));
        M = fmaxf(M, __shfl_xor_sync(0xffffffffu, M, 16));
        float f = __expf(m - M);
        f_s[t] = f;
        float L = lv * f;
        L += __shfl_xor_sync(0xffffffffu, L, 4);
        L += __shfl_xor_sync(0xffffffffu, L, 8);
        L += __shfl_xor_sync(0xffffffffu, L, 16);
        if (t < 4) {
            float qm = (float)((const int*)(sm + BF_QM))[0];
            sc_s[t] = qm / L;
        }
    }
    __syncthreads();

    {
        int d = t & 63, h = t >> 6;
        float S = 0.f;
        #pragma unroll
        for (int s = 0; s < SPLIT; s++)
            S += pacc_s[s * (HH * DD) + h * DD + d] * f_s[s * HH + h];
        s_sm[h * DD + d] = S * sc_s[h];
    }
    __syncthreads();

    {
        int j = t & 63, q = t >> 6;
        int h = j >> 4;
        float a = 0.f;
        #pragma unroll
        for (int d = q * 16; d < q * 16 + 16; d++) a += s_sm[h * DD + d] * wv_s[d * 64 + j];
        part_s[t] = a;
    }
    __syncthreads();
    if (t < 64) {
        float o = part_s[t] + part_s[64 + t] + part_s[128 + t] + part_s[192 + t];
        res_s[t] = o + q_s[t];
    }
    CP_WAIT_GROUP(1);
    __syncthreads();

    {
        float a = fb1_s[t];
        #pragma unroll
        for (int j = 0; j < 64; j++) a += res_s[j] * fw1_s[j * 256 + t];
        hid_s[t] = (a > 0.f) ? a : 0.2f * a;
    }
    CP_WAIT_GROUP(0);
    __syncthreads();

    {
        int j = t & 63, mq = t >> 6;
        float a = 0.f;
        #pragma unroll
        for (int m = mq * 64; m < mq * 64 + 64; m++) a += hid_s[m] * fw2_s[m * 64 + j];
        part_s[t] = a;
    }
    __syncthreads();
    if (t < 64) {
        out[b * 64 + t] = res_s[t] + fb2_s[t]
                        + part_s[t] + part_s[64 + t] + part_s[128 + t] + part_s[192 + t];
    }
}

extern "C" void kernel_launch(void* const* d_in, const int* in_sizes, int n_in,
                              void* d_out, int out_size)
{
    const float* queries = (const float*)d_in[0];
    const float* keys    = (const float*)d_in[1];
    const int*   qmask   = (const int*)d_in[2];
    const int*   kmask   = (const int*)d_in[3];
    const float* W_Q     = (const float*)d_in[4];
    const float* W_K     = (const float*)d_in[5];
    const float* W_V     = (const float*)d_in[6];
    const float* fw1     = (const float*)d_in[7];
    const float* fw2     = (const float*)d_in[8];
    const float* fb1     = (const float*)d_in[9];
    const float* fb2     = (const float*)d_in[10];
    float* out = (float*)d_out;

    cudaFuncSetAttribute(attn_partial_kernel,
                         cudaFuncAttributeMaxDynamicSharedMemorySize, ASM_BYTES);
    cudaFuncSetAttribute(combine_ffn_kernel,
                         cudaFuncAttributeMaxDynamicSharedMemorySize, BSM_BYTES);

    precompute_u_kernel<<<BB, 256>>>(queries, W_Q, W_K);
    attn_partial_kernel<<<dim3(SPLIT, BB), 256, ASM_BYTES>>>(keys, kmask);
    combine_ffn_kernel<<<BB, 256, BSM_BYTES>>>(queries, qmask, W_V, fw1, fw2, fb1, fb2, out);
}